// round 14
// baseline (speedup 1.0000x reference)
#include <cuda_runtime.h>
#include <cuda_fp16.h>
#include <stdint.h>

// Problem constants: B=8, CK=64, H=W=64 -> HW=4096
#define BATCH 8
#define CKDIM 64
#define HW    4096
#define NGROUPS 256           // (b, n_tile) groups: 8 * 32
#define GROUP_SIG 16          // pair-signals per group (32 m-tiles = 16 pairs)
#define NPAIRS 2048           // ticket space; iteration handles pairs c, c+2048
#define NPCTAS 152            // persistent CTAs (~1/SM)

// log2(e) folded into B scale so exp(a) == exp2(d)
#define BSCALE (0.125f * 1.4426950408889634f)

// SMEM layout
#define TILE_A1 0             // pair A tile (m even): 128x64 fp16 SW128, 16 KB
#define TILE_A2 16384         // pair A tile (m odd)
#define TILE_B  32768         // Qk*BSCALE
#define E0_OFF  49152         // pair1 tile0 exp fp16: 32 KB
#define E1_OFF  81920         // pair1 tile1 exp fp16: 32 KB
#define RED_OFF 114688        // 4 x 128 floats (non-atomic)
#define TKT_OFF 116736
#define SMEM_BYTES 116752

__device__ float g_sums[BATCH * HW];
__device__ unsigned g_cnt[NGROUPS];
__device__ unsigned g_ticket;

__global__ void init_kernel() {
    int i = blockIdx.x * blockDim.x + threadIdx.x;
    if (i < BATCH * HW) g_sums[i] = 0.0f;
    if (i < NGROUPS) g_cnt[i] = 0u;
    if (i == 0) g_ticket = 0u;
}

__device__ __forceinline__ uint32_t smem_u32(const void* p) {
    uint32_t a;
    asm("{ .reg .u64 t; cvta.to.shared.u64 t, %1; cvt.u32.u64 %0, t; }"
        : "=r"(a) : "l"(p));
    return a;
}
__device__ __forceinline__ uint32_t swz(uint32_t off) {
    return off ^ ((off >> 3) & 0x70);
}
__device__ __forceinline__ uint32_t pack2h(float v0, float v1) {
    __half2 h = __floats2half2_rn(v0, v1);
    return *(uint32_t*)&h;
}
__device__ __forceinline__ float ex2(float x) {
    float r;
    asm("ex2.approx.f32 %0, %1;" : "=f"(r) : "f"(x));
    return r;
}
__device__ __forceinline__ void sts128(uint32_t addr, uint32_t r0, uint32_t r1,
                                       uint32_t r2, uint32_t r3) {
    asm volatile("st.shared.v4.b32 [%0], {%1,%2,%3,%4};"
                 :: "r"(addr), "r"(r0), "r"(r1), "r"(r2), "r"(r3));
}
__device__ __forceinline__ void lds128(uint32_t addr, uint32_t* r) {
    asm volatile("ld.shared.v4.b32 {%0,%1,%2,%3}, [%4];"
                 : "=r"(r[0]), "=r"(r[1]), "=r"(r[2]), "=r"(r[3]) : "r"(addr));
}
__device__ __forceinline__ void ldsm4(uint32_t addr, uint32_t* r) {
    asm volatile("ldmatrix.sync.aligned.m8n8.x4.shared.b16 {%0,%1,%2,%3}, [%4];"
                 : "=r"(r[0]), "=r"(r[1]), "=r"(r[2]), "=r"(r[3]) : "r"(addr));
}
__device__ __forceinline__ void mma16816(float* d, const uint32_t* a, const uint32_t* b) {
    asm volatile(
        "mma.sync.aligned.m16n8k16.row.col.f32.f16.f16.f32 "
        "{%0,%1,%2,%3}, {%4,%5,%6,%7}, {%8,%9}, {%0,%1,%2,%3};"
        : "+f"(d[0]), "+f"(d[1]), "+f"(d[2]), "+f"(d[3])
        : "r"(a[0]), "r"(a[1]), "r"(a[2]), "r"(a[3]), "r"(b[0]), "r"(b[1]));
}
__device__ __forceinline__ void signal_grp(unsigned* cnt) {
    asm volatile("red.release.gpu.global.add.u32 [%0], %1;"
                 :: "l"(cnt), "r"(1u) : "memory");
}
__device__ __forceinline__ void wait_grp(unsigned* cnt) {
    unsigned v;
    do {
        asm volatile("ld.acquire.gpu.global.u32 %0, [%1];"
                     : "=r"(v) : "l"(cnt) : "memory");
        if (v < GROUP_SIG) __nanosleep(64);
    } while (v < GROUP_SIG);
}

// Load one 128x64 fp16 tile (conflict-free STS.128), 512 threads.
__device__ __forceinline__ void load_half(uint32_t dst, const float* __restrict__ P,
                                          float scale, int tid) {
    const int lane = tid & 31;
#pragma unroll
    for (int it = 0; it < 2; it++) {
        const int slot = (tid >> 5) * 2 + it;
        const int rg = slot >> 3, kb = slot & 7;
        const int r = rg * 32 + lane;
        const int c0 = kb * 8;
        float v[8];
#pragma unroll
        for (int j = 0; j < 8; j++) v[j] = P[(size_t)(c0 + j) * HW + r] * scale;
        uint32_t w[4];
#pragma unroll
        for (int j = 0; j < 4; j++) w[j] = pack2h(v[2 * j], v[2 * j + 1]);
        sts128(dst + swz((uint32_t)(r * 128 + kb * 16)), w[0], w[1], w[2], w[3]);
    }
}
__device__ __forceinline__ void load_pair(uint32_t sb, const float* Ap,
                                          const float* Bp, int tid) {
    load_half(sb + TILE_A1, Ap, 1.0f, tid);
    load_half(sb + TILE_A2, Ap + 128, 1.0f, tid);
    load_half(sb + TILE_B, Bp, BSCALE, tid);
}

// Interleaved pair mainloop: B fragments loaded once per ks, feed both A tiles.
__device__ __forceinline__ void mma_pair(uint32_t sb, float a1[2][4][4],
                                         float a2[2][4][4], int wm, int wn, int lane) {
    const int a_row = wm * 32 + (lane & 7) + ((lane >> 3) & 1) * 8;
    const int a_kb  = (lane >> 4) * 16;
    const int b_row = wn * 32 + (lane & 7) + (lane >> 4) * 8;
    const int b_kb  = ((lane >> 3) & 1) * 16;
#pragma unroll
    for (int ks = 0; ks < 4; ks++) {
        const int kbase = ks * 32;
        uint32_t bf[8], ah1[2][4], ah2[2][4];
        ldsm4(sb + TILE_B + swz((uint32_t)(b_row * 128 + kbase + b_kb)), &bf[0]);
        ldsm4(sb + TILE_B + swz((uint32_t)((b_row + 16) * 128 + kbase + b_kb)), &bf[4]);
        ldsm4(sb + TILE_A1 + swz((uint32_t)(a_row * 128 + kbase + a_kb)), ah1[0]);
        ldsm4(sb + TILE_A1 + swz((uint32_t)((a_row + 16) * 128 + kbase + a_kb)), ah1[1]);
        ldsm4(sb + TILE_A2 + swz((uint32_t)(a_row * 128 + kbase + a_kb)), ah2[0]);
        ldsm4(sb + TILE_A2 + swz((uint32_t)((a_row + 16) * 128 + kbase + a_kb)), ah2[1]);
#pragma unroll
        for (int mi = 0; mi < 2; mi++)
#pragma unroll
            for (int ni = 0; ni < 4; ni++) {
                mma16816(a1[mi][ni], ah1[mi], &bf[ni * 2]);
                mma16816(a2[mi][ni], ah2[mi], &bf[ni * 2]);
            }
    }
}

// exp2 both accs, combined column sums, optional fp16 E park, non-atomic RED.
__device__ __forceinline__ void exp_pair(uint32_t sb, float a1[2][4][4],
                                         float a2[2][4][4], int tid, int lane,
                                         int wm, int wn, bool write_e) {
    float cs[8];
#pragma unroll
    for (int q = 0; q < 8; q++) cs[q] = 0.0f;
#pragma unroll
    for (int mi = 0; mi < 2; mi++)
#pragma unroll
        for (int ni = 0; ni < 4; ni++) {
#pragma unroll
            for (int q = 0; q < 4; q++) {
                a1[mi][ni][q] = ex2(a1[mi][ni][q]);
                a2[mi][ni][q] = ex2(a2[mi][ni][q]);
            }
            cs[2 * ni]     += a1[mi][ni][0] + a1[mi][ni][2] + a2[mi][ni][0] + a2[mi][ni][2];
            cs[2 * ni + 1] += a1[mi][ni][1] + a1[mi][ni][3] + a2[mi][ni][1] + a2[mi][ni][3];
        }
    if (write_e) {
#pragma unroll
        for (int ni = 0; ni < 4; ni++) {
            uint32_t w[4];
#pragma unroll
            for (int q = 0; q < 4; q++) w[q] = pack2h(a1[0][ni][q], a1[1][ni][q]);
            sts128(sb + E0_OFF + (uint32_t)((ni * 512 + tid) * 16), w[0], w[1], w[2], w[3]);
#pragma unroll
            for (int q = 0; q < 4; q++) w[q] = pack2h(a2[0][ni][q], a2[1][ni][q]);
            sts128(sb + E1_OFF + (uint32_t)((ni * 512 + tid) * 16), w[0], w[1], w[2], w[3]);
        }
    }
#pragma unroll
    for (int msk = 4; msk < 32; msk <<= 1)
#pragma unroll
        for (int q = 0; q < 8; q++)
            cs[q] += __shfl_xor_sync(0xFFFFFFFFu, cs[q], msk);
    if (lane < 4) {
#pragma unroll
        for (int ni = 0; ni < 4; ni++) {
            uint32_t base = (uint32_t)(RED_OFF + (wm * 128 + wn * 32 + ni * 8 + 2 * lane) * 4);
            asm volatile("st.shared.b32 [%0], %1;" :: "r"(sb + base), "f"(cs[2 * ni]));
            asm volatile("st.shared.b32 [%0], %1;" :: "r"(sb + base + 4), "f"(cs[2 * ni + 1]));
        }
    }
}

__device__ __forceinline__ void store_from_E(uint32_t sb, uint32_t eoff,
                                             const float* rs, float* __restrict__ outb,
                                             int tid, int mrow_l, int ncl) {
#pragma unroll
    for (int ni = 0; ni < 4; ni++) {
        uint32_t w[4];
        lds128(sb + eoff + (uint32_t)((ni * 512 + tid) * 16), w);
        float e0[4], e1[4];
#pragma unroll
        for (int q = 0; q < 4; q++) {
            float2 p = __half22float2(*(__half2*)&w[q]);
            e0[q] = p.x; e1[q] = p.y;
        }
        size_t ro = (size_t)mrow_l * HW + ncl + ni * 8;
        __stcs((float2*)(outb + ro),
               make_float2(e0[0] * rs[2 * ni], e0[1] * rs[2 * ni + 1]));
        __stcs((float2*)(outb + ro + (size_t)8 * HW),
               make_float2(e0[2] * rs[2 * ni], e0[3] * rs[2 * ni + 1]));
        ro += (size_t)16 * HW;
        __stcs((float2*)(outb + ro),
               make_float2(e1[0] * rs[2 * ni], e1[1] * rs[2 * ni + 1]));
        __stcs((float2*)(outb + ro + (size_t)8 * HW),
               make_float2(e1[2] * rs[2 * ni], e1[3] * rs[2 * ni + 1]));
    }
}
__device__ __forceinline__ void store_from_regs(const float acc[2][4][4],
                                                const float* rs, float* __restrict__ outb,
                                                int mrow_l, int ncl) {
#pragma unroll
    for (int mi = 0; mi < 2; mi++)
#pragma unroll
        for (int ni = 0; ni < 4; ni++) {
            size_t ro = (size_t)(mrow_l + mi * 16) * HW + ncl + ni * 8;
            __stcs((float2*)(outb + ro),
                   make_float2(acc[mi][ni][0] * rs[2 * ni], acc[mi][ni][1] * rs[2 * ni + 1]));
            __stcs((float2*)(outb + ro + (size_t)8 * HW),
                   make_float2(acc[mi][ni][2] * rs[2 * ni], acc[mi][ni][3] * rs[2 * ni + 1]));
        }
}

// Persistent kernel. DEADLOCK-SAFE ORDERING: the next ticket is drawn only
// AFTER both group waits pass. Every drawn ticket is therefore signaled
// before its holder waits; a blocked CTA's missing window member is undrawn,
// and >=136 CTAs on earlier (complete) windows keep advancing the frontier.
// Prefetch of the next pair1 overlaps the two store phases.
__global__ __launch_bounds__(512, 1)
void gemm_softmax_fused(const float* __restrict__ Mk, const float* __restrict__ Qk,
                        float* __restrict__ out) {
    extern __shared__ char smem[];
    const uint32_t sb = smem_u32(smem);
    const int tid = threadIdx.x, lane = tid & 31, wid = tid >> 5;
    const int wm = wid >> 2, wn = wid & 3;
    float* RED = (float*)(smem + RED_OFF);
    volatile unsigned* TKT = (volatile unsigned*)(smem + TKT_OFF);

    const int mrow_l = wm * 32 + (lane >> 2);
    const int ncl    = wn * 32 + 2 * (lane & 3);

    if (tid == 0) *TKT = atomicAdd(&g_ticket, 1u);
    __syncthreads();
    unsigned c = *TKT;

    // prologue: load first pair1 tiles
    if (c < NPAIRS) {
        const int g1 = (int)(c >> 4), mp1 = (int)(c & 15u);
        load_pair(sb, Mk + (size_t)(g1 >> 5) * CKDIM * HW + mp1 * 256,
                  Qk + (size_t)(g1 >> 5) * CKDIM * HW + (g1 & 31) * 128, tid);
    }

    while (c < NPAIRS) {
        const unsigned p2 = c + NPAIRS;
        const int g1 = (int)(c >> 4),  mp1 = (int)(c & 15u);
        const int g2 = (int)(p2 >> 4), mp2 = (int)(p2 & 15u);
        const int n1 = (g1 & 31) * 128, b1 = g1 >> 5;
        const int n2 = (g2 & 31) * 128, b2 = g2 >> 5;
        float* gs1 = &g_sums[b1 * HW + n1];
        float* gs2 = &g_sums[b2 * HW + n2];

        float acc1[2][4][4], acc2[2][4][4];
#pragma unroll
        for (int i = 0; i < 2; i++)
#pragma unroll
            for (int j = 0; j < 4; j++)
#pragma unroll
                for (int q = 0; q < 4; q++) { acc1[i][j][q] = 0.f; acc2[i][j][q] = 0.f; }

        __syncthreads();                   // pair1 tiles visible
        mma_pair(sb, acc1, acc2, wm, wn, lane);
        exp_pair(sb, acc1, acc2, tid, lane, wm, wn, true);
        __syncthreads();                   // E + RED done; tile bufs free
        if (tid < 128)
            atomicAdd(&gs1[tid], RED[tid] + RED[128 + tid] + RED[256 + tid] + RED[384 + tid]);

        // pair 2 loads
        load_pair(sb, Mk + (size_t)b2 * CKDIM * HW + mp2 * 256,
                  Qk + (size_t)b2 * CKDIM * HW + n2, tid);
        __syncthreads();                   // gs1 atomics + loads visible
        if (tid == 0) signal_grp(&g_cnt[g1]);

#pragma unroll
        for (int i = 0; i < 2; i++)
#pragma unroll
            for (int j = 0; j < 4; j++)
#pragma unroll
                for (int q = 0; q < 4; q++) { acc1[i][j][q] = 0.f; acc2[i][j][q] = 0.f; }
        mma_pair(sb, acc1, acc2, wm, wn, lane);
        exp_pair(sb, acc1, acc2, tid, lane, wm, wn, false);
        __syncthreads();
        if (tid < 128)
            atomicAdd(&gs2[tid], RED[tid] + RED[128 + tid] + RED[256 + tid] + RED[384 + tid]);
        __syncthreads();                   // gs2 atomics complete

        // signals -> BOTH waits -> only then draw the next ticket
        if (tid == 0) {
            signal_grp(&g_cnt[g2]);
            wait_grp(&g_cnt[g1]);
            wait_grp(&g_cnt[g2]);
            *TKT = atomicAdd(&g_ticket, 1u);
        }
        __syncthreads();
        const unsigned cn = *TKT;

        // prefetch next pair1 (tile buffers free; overlaps the stores below)
        if (cn < NPAIRS) {
            const int g1n = (int)(cn >> 4), mp1n = (int)(cn & 15u);
            load_pair(sb, Mk + (size_t)(g1n >> 5) * CKDIM * HW + mp1n * 256,
                      Qk + (size_t)(g1n >> 5) * CKDIM * HW + (g1n & 31) * 128, tid);
        }

        // store pair 1 from E
        {
            float rs[8];
#pragma unroll
            for (int ni = 0; ni < 4; ni++) {
                rs[2 * ni]     = __fdividef(1.0f, __ldcg(&gs1[ncl + ni * 8]));
                rs[2 * ni + 1] = __fdividef(1.0f, __ldcg(&gs1[ncl + ni * 8 + 1]));
            }
            float* outb = out + (size_t)(b1 * HW + mp1 * 256) * HW + n1;
            store_from_E(sb, E0_OFF, rs, outb, tid, mrow_l, ncl);
            store_from_E(sb, E1_OFF, rs, outb + (size_t)128 * HW, tid, mrow_l, ncl);
        }

        // store pair 2 from registers
        {
            float rs[8];
#pragma unroll
            for (int ni = 0; ni < 4; ni++) {
                rs[2 * ni]     = __fdividef(1.0f, __ldcg(&gs2[ncl + ni * 8]));
                rs[2 * ni + 1] = __fdividef(1.0f, __ldcg(&gs2[ncl + ni * 8 + 1]));
            }
            float* outb = out + (size_t)(b2 * HW + mp2 * 256) * HW + n2;
            store_from_regs(acc1, rs, outb, mrow_l, ncl);
            store_from_regs(acc2, rs, outb + (size_t)128 * HW, mrow_l, ncl);
        }

        c = cn;
    }
}

extern "C" void kernel_launch(void* const* d_in, const int* in_sizes, int n_in,
                              void* d_out, int out_size) {
    const float* Mk = (const float*)d_in[0];
    const float* Qk = (const float*)d_in[1];
    float* out = (float*)d_out;

    cudaFuncSetAttribute(gemm_softmax_fused,
                         cudaFuncAttributeMaxDynamicSharedMemorySize, SMEM_BYTES);

    init_kernel<<<(BATCH * HW + 255) / 256, 256>>>();

    gemm_softmax_fused<<<NPCTAS, 512, SMEM_BYTES>>>(Mk, Qk, out);
}

// round 15
// speedup vs baseline: 1.1183x; 1.1183x over previous
#include <cuda_runtime.h>
#include <cuda_fp16.h>
#include <stdint.h>

// Problem constants: B=8, CK=64, H=W=64 -> HW=4096
#define BATCH 8
#define CKDIM 64
#define HW    4096
#define NGROUPS 256           // (b, n_tile) groups: 8 * 32
#define GROUP_SIG 16          // pair-signals per group (32 m-tiles = 16 pairs)
#define NPAIRS 2048           // pair ids; iteration handles pairs c, c+2048
#define NPCTAS 152            // persistent CTAs (~1/SM)

// log2(e) folded into B scale so exp(a) == exp2(d)
#define BSCALE (0.125f * 1.4426950408889634f)

// SMEM layout
#define TILE_A1 0             // pair A tile (m even): 128x64 fp16 SW128, 16 KB
#define TILE_A2 16384         // pair A tile (m odd)
#define TILE_B  32768         // Qk*BSCALE
#define E0_OFF  49152         // pair1 tile0 exp fp16: 32 KB
#define E1_OFF  81920         // pair1 tile1 exp fp16: 32 KB
#define RED_OFF 114688        // 4 x 128 floats (non-atomic)
#define SMEM_BYTES 116736

__device__ float g_sums[BATCH * HW];
__device__ unsigned g_cnt[NGROUPS];

__global__ void init_kernel() {
    int i = blockIdx.x * blockDim.x + threadIdx.x;
    if (i < BATCH * HW) g_sums[i] = 0.0f;
    if (i < NGROUPS) g_cnt[i] = 0u;
}

__device__ __forceinline__ uint32_t smem_u32(const void* p) {
    uint32_t a;
    asm("{ .reg .u64 t; cvta.to.shared.u64 t, %1; cvt.u32.u64 %0, t; }"
        : "=r"(a) : "l"(p));
    return a;
}
__device__ __forceinline__ uint32_t swz(uint32_t off) {
    return off ^ ((off >> 3) & 0x70);
}
__device__ __forceinline__ uint32_t pack2h(float v0, float v1) {
    __half2 h = __floats2half2_rn(v0, v1);
    return *(uint32_t*)&h;
}
__device__ __forceinline__ float ex2(float x) {
    float r;
    asm("ex2.approx.f32 %0, %1;" : "=f"(r) : "f"(x));
    return r;
}
__device__ __forceinline__ void sts128(uint32_t addr, uint32_t r0, uint32_t r1,
                                       uint32_t r2, uint32_t r3) {
    asm volatile("st.shared.v4.b32 [%0], {%1,%2,%3,%4};"
                 :: "r"(addr), "r"(r0), "r"(r1), "r"(r2), "r"(r3));
}
__device__ __forceinline__ void lds128(uint32_t addr, uint32_t* r) {
    asm volatile("ld.shared.v4.b32 {%0,%1,%2,%3}, [%4];"
                 : "=r"(r[0]), "=r"(r[1]), "=r"(r[2]), "=r"(r[3]) : "r"(addr));
}
__device__ __forceinline__ void ldsm4(uint32_t addr, uint32_t* r) {
    asm volatile("ldmatrix.sync.aligned.m8n8.x4.shared.b16 {%0,%1,%2,%3}, [%4];"
                 : "=r"(r[0]), "=r"(r[1]), "=r"(r[2]), "=r"(r[3]) : "r"(addr));
}
__device__ __forceinline__ void mma16816(float* d, const uint32_t* a, const uint32_t* b) {
    asm volatile(
        "mma.sync.aligned.m16n8k16.row.col.f32.f16.f16.f32 "
        "{%0,%1,%2,%3}, {%4,%5,%6,%7}, {%8,%9}, {%0,%1,%2,%3};"
        : "+f"(d[0]), "+f"(d[1]), "+f"(d[2]), "+f"(d[3])
        : "r"(a[0]), "r"(a[1]), "r"(a[2]), "r"(a[3]), "r"(b[0]), "r"(b[1]));
}
__device__ __forceinline__ void signal_grp(unsigned* cnt) {
    asm volatile("red.release.gpu.global.add.u32 [%0], %1;"
                 :: "l"(cnt), "r"(1u) : "memory");
}
__device__ __forceinline__ void wait_grp(unsigned* cnt) {
    unsigned v;
    do {
        asm volatile("ld.acquire.gpu.global.u32 %0, [%1];"
                     : "=r"(v) : "l"(cnt) : "memory");
        if (v < GROUP_SIG) __nanosleep(64);
    } while (v < GROUP_SIG);
}

// Load one 128x64 fp16 tile (conflict-free STS.128), 512 threads.
__device__ __forceinline__ void load_half(uint32_t dst, const float* __restrict__ P,
                                          float scale, int tid) {
    const int lane = tid & 31;
#pragma unroll
    for (int it = 0; it < 2; it++) {
        const int slot = (tid >> 5) * 2 + it;
        const int rg = slot >> 3, kb = slot & 7;
        const int r = rg * 32 + lane;
        const int c0 = kb * 8;
        float v[8];
#pragma unroll
        for (int j = 0; j < 8; j++) v[j] = P[(size_t)(c0 + j) * HW + r] * scale;
        uint32_t w[4];
#pragma unroll
        for (int j = 0; j < 4; j++) w[j] = pack2h(v[2 * j], v[2 * j + 1]);
        sts128(dst + swz((uint32_t)(r * 128 + kb * 16)), w[0], w[1], w[2], w[3]);
    }
}
__device__ __forceinline__ void load_pair(uint32_t sb, const float* __restrict__ Mk,
                                          const float* __restrict__ Qk,
                                          unsigned pr, int tid) {
    const int g = (int)(pr >> 4), mp = (int)(pr & 15u);
    const float* Ap = Mk + (size_t)(g >> 5) * CKDIM * HW + mp * 256;
    const float* Bp = Qk + (size_t)(g >> 5) * CKDIM * HW + (g & 31) * 128;
    load_half(sb + TILE_A1, Ap, 1.0f, tid);
    load_half(sb + TILE_A2, Ap + 128, 1.0f, tid);
    load_half(sb + TILE_B, Bp, BSCALE, tid);
}

// Interleaved pair mainloop: B fragments loaded once per ks, feed both A tiles.
__device__ __forceinline__ void mma_pair(uint32_t sb, float a1[2][4][4],
                                         float a2[2][4][4], int wm, int wn, int lane) {
    const int a_row = wm * 32 + (lane & 7) + ((lane >> 3) & 1) * 8;
    const int a_kb  = (lane >> 4) * 16;
    const int b_row = wn * 32 + (lane & 7) + (lane >> 4) * 8;
    const int b_kb  = ((lane >> 3) & 1) * 16;
#pragma unroll
    for (int ks = 0; ks < 4; ks++) {
        const int kbase = ks * 32;
        uint32_t bf[8], ah1[2][4], ah2[2][4];
        ldsm4(sb + TILE_B + swz((uint32_t)(b_row * 128 + kbase + b_kb)), &bf[0]);
        ldsm4(sb + TILE_B + swz((uint32_t)((b_row + 16) * 128 + kbase + b_kb)), &bf[4]);
        ldsm4(sb + TILE_A1 + swz((uint32_t)(a_row * 128 + kbase + a_kb)), ah1[0]);
        ldsm4(sb + TILE_A1 + swz((uint32_t)((a_row + 16) * 128 + kbase + a_kb)), ah1[1]);
        ldsm4(sb + TILE_A2 + swz((uint32_t)(a_row * 128 + kbase + a_kb)), ah2[0]);
        ldsm4(sb + TILE_A2 + swz((uint32_t)((a_row + 16) * 128 + kbase + a_kb)), ah2[1]);
#pragma unroll
        for (int mi = 0; mi < 2; mi++)
#pragma unroll
            for (int ni = 0; ni < 4; ni++) {
                mma16816(a1[mi][ni], ah1[mi], &bf[ni * 2]);
                mma16816(a2[mi][ni], ah2[mi], &bf[ni * 2]);
            }
    }
}

// exp2 both accs, combined column sums, optional fp16 E park, non-atomic RED.
__device__ __forceinline__ void exp_pair(uint32_t sb, float a1[2][4][4],
                                         float a2[2][4][4], int tid, int lane,
                                         int wm, int wn, bool write_e) {
    float cs[8];
#pragma unroll
    for (int q = 0; q < 8; q++) cs[q] = 0.0f;
#pragma unroll
    for (int mi = 0; mi < 2; mi++)
#pragma unroll
        for (int ni = 0; ni < 4; ni++) {
#pragma unroll
            for (int q = 0; q < 4; q++) {
                a1[mi][ni][q] = ex2(a1[mi][ni][q]);
                a2[mi][ni][q] = ex2(a2[mi][ni][q]);
            }
            cs[2 * ni]     += a1[mi][ni][0] + a1[mi][ni][2] + a2[mi][ni][0] + a2[mi][ni][2];
            cs[2 * ni + 1] += a1[mi][ni][1] + a1[mi][ni][3] + a2[mi][ni][1] + a2[mi][ni][3];
        }
    if (write_e) {
#pragma unroll
        for (int ni = 0; ni < 4; ni++) {
            uint32_t w[4];
#pragma unroll
            for (int q = 0; q < 4; q++) w[q] = pack2h(a1[0][ni][q], a1[1][ni][q]);
            sts128(sb + E0_OFF + (uint32_t)((ni * 512 + tid) * 16), w[0], w[1], w[2], w[3]);
#pragma unroll
            for (int q = 0; q < 4; q++) w[q] = pack2h(a2[0][ni][q], a2[1][ni][q]);
            sts128(sb + E1_OFF + (uint32_t)((ni * 512 + tid) * 16), w[0], w[1], w[2], w[3]);
        }
    }
#pragma unroll
    for (int msk = 4; msk < 32; msk <<= 1)
#pragma unroll
        for (int q = 0; q < 8; q++)
            cs[q] += __shfl_xor_sync(0xFFFFFFFFu, cs[q], msk);
    if (lane < 4) {
#pragma unroll
        for (int ni = 0; ni < 4; ni++) {
            uint32_t base = (uint32_t)(RED_OFF + (wm * 128 + wn * 32 + ni * 8 + 2 * lane) * 4);
            asm volatile("st.shared.b32 [%0], %1;" :: "r"(sb + base), "f"(cs[2 * ni]));
            asm volatile("st.shared.b32 [%0], %1;" :: "r"(sb + base + 4), "f"(cs[2 * ni + 1]));
        }
    }
}

__device__ __forceinline__ void store_from_E(uint32_t sb, uint32_t eoff,
                                             const float* rs, float* __restrict__ outb,
                                             int tid, int mrow_l, int ncl) {
#pragma unroll
    for (int ni = 0; ni < 4; ni++) {
        uint32_t w[4];
        lds128(sb + eoff + (uint32_t)((ni * 512 + tid) * 16), w);
        float e0[4], e1[4];
#pragma unroll
        for (int q = 0; q < 4; q++) {
            float2 p = __half22float2(*(__half2*)&w[q]);
            e0[q] = p.x; e1[q] = p.y;
        }
        size_t ro = (size_t)mrow_l * HW + ncl + ni * 8;
        __stcs((float2*)(outb + ro),
               make_float2(e0[0] * rs[2 * ni], e0[1] * rs[2 * ni + 1]));
        __stcs((float2*)(outb + ro + (size_t)8 * HW),
               make_float2(e0[2] * rs[2 * ni], e0[3] * rs[2 * ni + 1]));
        ro += (size_t)16 * HW;
        __stcs((float2*)(outb + ro),
               make_float2(e1[0] * rs[2 * ni], e1[1] * rs[2 * ni + 1]));
        __stcs((float2*)(outb + ro + (size_t)8 * HW),
               make_float2(e1[2] * rs[2 * ni], e1[3] * rs[2 * ni + 1]));
    }
}
__device__ __forceinline__ void store_from_regs(const float acc[2][4][4],
                                                const float* rs, float* __restrict__ outb,
                                                int mrow_l, int ncl) {
#pragma unroll
    for (int mi = 0; mi < 2; mi++)
#pragma unroll
        for (int ni = 0; ni < 4; ni++) {
            size_t ro = (size_t)(mrow_l + mi * 16) * HW + ncl + ni * 8;
            __stcs((float2*)(outb + ro),
                   make_float2(acc[mi][ni][0] * rs[2 * ni], acc[mi][ni][1] * rs[2 * ni + 1]));
            __stcs((float2*)(outb + ro + (size_t)8 * HW),
                   make_float2(acc[mi][ni][2] * rs[2 * ni], acc[mi][ni][3] * rs[2 * ni + 1]));
        }
}

// Persistent, STATIC grid-stride schedule (no ticket atomics). CTA i handles
// pairs i, i+152, ... Next pair1 is known statically, so its prefetch precedes
// the waits — full overlap AND deadlock safety (signal-before-wait per level;
// window straddles reference strictly earlier levels -> no cycle).
__global__ __launch_bounds__(512, 1)
void gemm_softmax_fused(const float* __restrict__ Mk, const float* __restrict__ Qk,
                        float* __restrict__ out) {
    extern __shared__ char smem[];
    const uint32_t sb = smem_u32(smem);
    const int tid = threadIdx.x, lane = tid & 31, wid = tid >> 5;
    const int wm = wid >> 2, wn = wid & 3;
    float* RED = (float*)(smem + RED_OFF);

    const int mrow_l = wm * 32 + (lane >> 2);
    const int ncl    = wn * 32 + 2 * (lane & 3);

    unsigned c = blockIdx.x;
    if (c < NPAIRS)
        load_pair(sb, Mk, Qk, c, tid);     // prologue pair1 load

    for (; c < NPAIRS; c += NPCTAS) {
        const unsigned p2 = c + NPAIRS;
        const int g1 = (int)(c >> 4),  mp1 = (int)(c & 15u);
        const int g2 = (int)(p2 >> 4), mp2 = (int)(p2 & 15u);
        const int n1 = (g1 & 31) * 128, b1 = g1 >> 5;
        const int n2 = (g2 & 31) * 128, b2 = g2 >> 5;
        float* gs1 = &g_sums[b1 * HW + n1];
        float* gs2 = &g_sums[b2 * HW + n2];

        float acc1[2][4][4], acc2[2][4][4];
#pragma unroll
        for (int i = 0; i < 2; i++)
#pragma unroll
            for (int j = 0; j < 4; j++)
#pragma unroll
                for (int q = 0; q < 4; q++) { acc1[i][j][q] = 0.f; acc2[i][j][q] = 0.f; }

        __syncthreads();                   // pair1 tiles visible
        mma_pair(sb, acc1, acc2, wm, wn, lane);
        exp_pair(sb, acc1, acc2, tid, lane, wm, wn, true);
        __syncthreads();                   // E + RED done; tile bufs free
        if (tid < 128)
            atomicAdd(&gs1[tid], RED[tid] + RED[128 + tid] + RED[256 + tid] + RED[384 + tid]);

        // pair 2 loads
        load_pair(sb, Mk, Qk, p2, tid);
        __syncthreads();                   // gs1 atomics + loads visible
        if (tid == 0) signal_grp(&g_cnt[g1]);

#pragma unroll
        for (int i = 0; i < 2; i++)
#pragma unroll
            for (int j = 0; j < 4; j++)
#pragma unroll
                for (int q = 0; q < 4; q++) { acc1[i][j][q] = 0.f; acc2[i][j][q] = 0.f; }
        mma_pair(sb, acc1, acc2, wm, wn, lane);
        exp_pair(sb, acc1, acc2, tid, lane, wm, wn, false);
        __syncthreads();
        if (tid < 128)
            atomicAdd(&gs2[tid], RED[tid] + RED[128 + tid] + RED[256 + tid] + RED[384 + tid]);
        __syncthreads();                   // gs2 atomics complete
        if (tid == 0) signal_grp(&g_cnt[g2]);

        // prefetch next iteration's pair1 BEFORE the waits (index is static)
        const unsigned cn = c + NPCTAS;
        if (cn < NPAIRS)
            load_pair(sb, Mk, Qk, cn, tid);

        // store pair 1 from E (wait slack = pair2 compute + prefetch)
        if (tid == 0) wait_grp(&g_cnt[g1]);
        __syncthreads();
        {
            float rs[8];
#pragma unroll
            for (int ni = 0; ni < 4; ni++) {
                rs[2 * ni]     = __fdividef(1.0f, __ldcg(&gs1[ncl + ni * 8]));
                rs[2 * ni + 1] = __fdividef(1.0f, __ldcg(&gs1[ncl + ni * 8 + 1]));
            }
            float* outb = out + (size_t)(b1 * HW + mp1 * 256) * HW + n1;
            store_from_E(sb, E0_OFF, rs, outb, tid, mrow_l, ncl);
            store_from_E(sb, E1_OFF, rs, outb + (size_t)128 * HW, tid, mrow_l, ncl);
        }

        // store pair 2 from registers
        if (tid == 0) wait_grp(&g_cnt[g2]);
        __syncthreads();
        {
            float rs[8];
#pragma unroll
            for (int ni = 0; ni < 4; ni++) {
                rs[2 * ni]     = __fdividef(1.0f, __ldcg(&gs2[ncl + ni * 8]));
                rs[2 * ni + 1] = __fdividef(1.0f, __ldcg(&gs2[ncl + ni * 8 + 1]));
            }
            float* outb = out + (size_t)(b2 * HW + mp2 * 256) * HW + n2;
            store_from_regs(acc1, rs, outb, mrow_l, ncl);
            store_from_regs(acc2, rs, outb + (size_t)128 * HW, mrow_l, ncl);
        }
    }
}

extern "C" void kernel_launch(void* const* d_in, const int* in_sizes, int n_in,
                              void* d_out, int out_size) {
    const float* Mk = (const float*)d_in[0];
    const float* Qk = (const float*)d_in[1];
    float* out = (float*)d_out;

    cudaFuncSetAttribute(gemm_softmax_fused,
                         cudaFuncAttributeMaxDynamicSharedMemorySize, SMEM_BYTES);

    init_kernel<<<(BATCH * HW + 255) / 256, 256>>>();

    gemm_softmax_fused<<<NPCTAS, 512, SMEM_BYTES>>>(Mk, Qk, out);
}